// round 2
// baseline (speedup 1.0000x reference)
#include <cuda_runtime.h>

#define THREADS 128
#define EPSF 1e-12f

__global__ __launch_bounds__(THREADS)
void sinkhorn_unmatched_kernel(
    const float* __restrict__ margins,
    const float* __restrict__ W1, const float* __restrict__ b1,
    const float* __restrict__ W2, const float* __restrict__ b2,
    const float* __restrict__ W3, const float* __restrict__ b3,
    const float* __restrict__ W4, const float* __restrict__ b4,
    float* __restrict__ out_mus, float* __restrict__ out_V, int B)
{
    // Shared weight staging. W4 padded to stride 12 so rows are float4-loadable.
    __shared__ float sW1[6 * 64];
    __shared__ float sb1[64];
    __shared__ float sW2[64 * 32];
    __shared__ float sb2[32];
    __shared__ float sW3[32 * 16];
    __shared__ float sb3[16];
    __shared__ float sW4[16 * 12];
    __shared__ float sb4[12];

    for (int i = threadIdx.x; i < 6 * 64; i += THREADS) sW1[i] = W1[i];
    for (int i = threadIdx.x; i < 64; i += THREADS) sb1[i] = b1[i];
    for (int i = threadIdx.x; i < 64 * 32; i += THREADS) sW2[i] = W2[i];
    for (int i = threadIdx.x; i < 32; i += THREADS) sb2[i] = b2[i];
    for (int i = threadIdx.x; i < 32 * 16; i += THREADS) sW3[i] = W3[i];
    for (int i = threadIdx.x; i < 16; i += THREADS) sb3[i] = b3[i];
    for (int i = threadIdx.x; i < 16 * 12; i += THREADS) {
        int r = i / 12, c = i % 12;
        sW4[i] = (c < 9) ? W4[r * 9 + c] : 0.0f;
    }
    for (int i = threadIdx.x; i < 12; i += THREADS) sb4[i] = (i < 9) ? b4[i] : 0.0f;
    __syncthreads();

    int row = blockIdx.x * THREADS + threadIdx.x;
    if (row >= B) return;

    // ---- load margins (row*24 bytes is 8B-aligned -> float2 loads) ----
    const float2* m2 = reinterpret_cast<const float2*>(margins);
    float2 ma = m2[row * 3 + 0];
    float2 mb = m2[row * 3 + 1];
    float2 mc = m2[row * 3 + 2];
    float x[6] = { ma.x, ma.y, mb.x, mb.y, mc.x, mc.y };

    // ---- layer 1: 6 -> 64 ----
    float h1[64];
    {
        const float4* b4v = reinterpret_cast<const float4*>(sb1);
        #pragma unroll
        for (int j = 0; j < 16; j++) {
            float4 bb = b4v[j];
            h1[4 * j + 0] = bb.x; h1[4 * j + 1] = bb.y;
            h1[4 * j + 2] = bb.z; h1[4 * j + 3] = bb.w;
        }
        #pragma unroll
        for (int i = 0; i < 6; i++) {
            float xi = x[i];
            const float4* wrow = reinterpret_cast<const float4*>(sW1 + i * 64);
            #pragma unroll
            for (int j = 0; j < 16; j++) {
                float4 w = wrow[j];
                h1[4 * j + 0] = fmaf(xi, w.x, h1[4 * j + 0]);
                h1[4 * j + 1] = fmaf(xi, w.y, h1[4 * j + 1]);
                h1[4 * j + 2] = fmaf(xi, w.z, h1[4 * j + 2]);
                h1[4 * j + 3] = fmaf(xi, w.w, h1[4 * j + 3]);
            }
        }
        #pragma unroll
        for (int j = 0; j < 64; j++) h1[j] = fmaxf(h1[j], 0.0f);
    }

    // ---- layer 2: 64 -> 32 ----
    float h2[32];
    {
        const float4* b4v = reinterpret_cast<const float4*>(sb2);
        #pragma unroll
        for (int k = 0; k < 8; k++) {
            float4 bb = b4v[k];
            h2[4 * k + 0] = bb.x; h2[4 * k + 1] = bb.y;
            h2[4 * k + 2] = bb.z; h2[4 * k + 3] = bb.w;
        }
        #pragma unroll
        for (int j = 0; j < 64; j++) {
            float hj = h1[j];
            const float4* wrow = reinterpret_cast<const float4*>(sW2 + j * 32);
            #pragma unroll
            for (int k = 0; k < 8; k++) {
                float4 w = wrow[k];
                h2[4 * k + 0] = fmaf(hj, w.x, h2[4 * k + 0]);
                h2[4 * k + 1] = fmaf(hj, w.y, h2[4 * k + 1]);
                h2[4 * k + 2] = fmaf(hj, w.z, h2[4 * k + 2]);
                h2[4 * k + 3] = fmaf(hj, w.w, h2[4 * k + 3]);
            }
        }
        #pragma unroll
        for (int k = 0; k < 32; k++) h2[k] = fmaxf(h2[k], 0.0f);
    }

    // ---- layer 3: 32 -> 16 ----
    float h3[16];
    {
        const float4* b4v = reinterpret_cast<const float4*>(sb3);
        #pragma unroll
        for (int k = 0; k < 4; k++) {
            float4 bb = b4v[k];
            h3[4 * k + 0] = bb.x; h3[4 * k + 1] = bb.y;
            h3[4 * k + 2] = bb.z; h3[4 * k + 3] = bb.w;
        }
        #pragma unroll
        for (int j = 0; j < 32; j++) {
            float hj = h2[j];
            const float4* wrow = reinterpret_cast<const float4*>(sW3 + j * 16);
            #pragma unroll
            for (int k = 0; k < 4; k++) {
                float4 w = wrow[k];
                h3[4 * k + 0] = fmaf(hj, w.x, h3[4 * k + 0]);
                h3[4 * k + 1] = fmaf(hj, w.y, h3[4 * k + 1]);
                h3[4 * k + 2] = fmaf(hj, w.z, h3[4 * k + 2]);
                h3[4 * k + 3] = fmaf(hj, w.w, h3[4 * k + 3]);
            }
        }
        #pragma unroll
        for (int k = 0; k < 16; k++) h3[k] = fmaxf(h3[k], 0.0f);
    }

    // ---- layer 4: 16 -> 9 (padded to 12) ----
    float pars[12];
    {
        const float4* b4v = reinterpret_cast<const float4*>(sb4);
        #pragma unroll
        for (int k = 0; k < 3; k++) {
            float4 bb = b4v[k];
            pars[4 * k + 0] = bb.x; pars[4 * k + 1] = bb.y;
            pars[4 * k + 2] = bb.z; pars[4 * k + 3] = bb.w;
        }
        #pragma unroll
        for (int j = 0; j < 16; j++) {
            float hj = h3[j];
            const float4* wrow = reinterpret_cast<const float4*>(sW4 + j * 12);
            #pragma unroll
            for (int k = 0; k < 3; k++) {
                float4 w = wrow[k];
                pars[4 * k + 0] = fmaf(hj, w.x, pars[4 * k + 0]);
                pars[4 * k + 1] = fmaf(hj, w.y, pars[4 * k + 1]);
                pars[4 * k + 2] = fmaf(hj, w.z, pars[4 * k + 2]);
                pars[4 * k + 3] = fmaf(hj, w.w, pars[4 * k + 3]);
            }
        }
    }

    // ---- head math ----
    float M0 = x[0], M1 = x[1], M2 = x[2];
    float F0 = x[3], F1 = x[4], F2 = x[5];

    float A00 = __expf(pars[0]);
    float A01 = __expf(pars[1]);
    float A10 = __expf(pars[2]);
    float A11 = __expf(pars[3]);
    float A02 = 1.0f, A12 = 1.0f, A20 = 1.0f, A21 = 1.0f, A22 = 1.0f;

    // sqs(x) = 0.02 + 0.96 * sigmoid(x)
    float shm0 = 0.02f + 0.96f * __fdividef(1.0f, 1.0f + __expf(-pars[4]));
    float shm1 = 0.02f + 0.96f * __fdividef(1.0f, 1.0f + __expf(-pars[5]));
    float shf0 = 0.02f + 0.96f * __fdividef(1.0f, 1.0f + __expf(-pars[6]));
    float shf1 = 0.02f + 0.96f * __fdividef(1.0f, 1.0f + __expf(-pars[7]));
    float V = __expf(pars[8]);

    // row targets (mucm0) / column targets (muc0f)
    float r0 = M0 * shm0, r1 = M1 * shm1, r2 = M2;
    float c0 = F0 * shf0, c1 = F1 * shf1, c2 = F2;
    // unmatched masses
    float um0 = M0 * (1.0f - shm0), um1 = M1 * (1.0f - shm1), um2 = 0.0f;
    float uf0 = F0 * (1.0f - shf0), uf1 = F1 * (1.0f - shf1), uf2 = 0.0f;

    // ---- Sinkhorn-Knopp, 10 iterations on 3x3 in registers ----
    #pragma unroll
    for (int it = 0; it < 10; it++) {
        // row normalize to r
        {
            float f0 = __fdividef(r0, A00 + A01 + A02 + EPSF);
            float f1 = __fdividef(r1, A10 + A11 + A12 + EPSF);
            float f2 = __fdividef(r2, A20 + A21 + A22 + EPSF);
            A00 *= f0; A01 *= f0; A02 *= f0;
            A10 *= f1; A11 *= f1; A12 *= f1;
            A20 *= f2; A21 *= f2; A22 *= f2;
        }
        // column normalize to c
        {
            float g0 = __fdividef(c0, A00 + A10 + A20 + EPSF);
            float g1 = __fdividef(c1, A01 + A11 + A21 + EPSF);
            float g2 = __fdividef(c2, A02 + A12 + A22 + EPSF);
            A00 *= g0; A10 *= g0; A20 *= g0;
            A01 *= g1; A11 *= g1; A21 *= g1;
            A02 *= g2; A12 *= g2; A22 *= g2;
        }
    }

    // ---- write output: mus [B,4,4] then V [B] ----
    float4* o = reinterpret_cast<float4*>(out_mus + (size_t)row * 16);
    o[0] = make_float4(A00, A01, A02, um0);
    o[1] = make_float4(A10, A11, A12, um1);
    o[2] = make_float4(A20, A21, A22, um2);
    o[3] = make_float4(uf0, uf1, uf2, 0.0f);
    out_V[row] = V;
}

extern "C" void kernel_launch(void* const* d_in, const int* in_sizes, int n_in,
                              void* d_out, int out_size)
{
    const float* margins = (const float*)d_in[0];
    const float* W1 = (const float*)d_in[1];
    const float* b1 = (const float*)d_in[2];
    const float* W2 = (const float*)d_in[3];
    const float* b2 = (const float*)d_in[4];
    const float* W3 = (const float*)d_in[5];
    const float* b3 = (const float*)d_in[6];
    const float* W4 = (const float*)d_in[7];
    const float* b4 = (const float*)d_in[8];

    int B = in_sizes[0] / 6;
    float* out_mus = (float*)d_out;
    float* out_V = (float*)d_out + (size_t)B * 16;

    int blocks = (B + THREADS - 1) / THREADS;
    sinkhorn_unmatched_kernel<<<blocks, THREADS>>>(
        margins, W1, b1, W2, b2, W3, b3, W4, b4, out_mus, out_V, B);
}

// round 3
// speedup vs baseline: 1.2043x; 1.2043x over previous
#include <cuda_runtime.h>

#define THREADS 128
#define EPSF 1e-12f

// ---- f32x2 packed helpers (sm_103a) ----
__device__ __forceinline__ unsigned long long pack2(float lo, float hi) {
    unsigned long long r;
    asm("mov.b64 %0, {%1, %2};" : "=l"(r) : "f"(lo), "f"(hi));
    return r;
}
__device__ __forceinline__ void unpack2(unsigned long long p, float& lo, float& hi) {
    asm("mov.b64 {%0, %1}, %2;" : "=f"(lo), "=f"(hi) : "l"(p));
}
__device__ __forceinline__ unsigned long long fma2(unsigned long long a,
                                                   unsigned long long b,
                                                   unsigned long long c) {
    unsigned long long d;
    asm("fma.rn.f32x2 %0, %1, %2, %3;" : "=l"(d) : "l"(a), "l"(b), "l"(c));
    return d;
}

// ---- per-row head math + Sinkhorn + store ----
__device__ __forceinline__ void head_and_store(
    const float* __restrict__ x,    // 6 margins for this row
    const float* __restrict__ pars, // 9 valid MLP outputs
    float* __restrict__ out_mus, float* __restrict__ out_V, int row)
{
    float M0 = x[0], M1 = x[1], M2 = x[2];
    float F0 = x[3], F1 = x[4], F2 = x[5];

    float A00 = __expf(pars[0]);
    float A01 = __expf(pars[1]);
    float A10 = __expf(pars[2]);
    float A11 = __expf(pars[3]);
    float A02 = 1.0f, A12 = 1.0f, A20 = 1.0f, A21 = 1.0f, A22 = 1.0f;

    float shm0 = 0.02f + 0.96f * __fdividef(1.0f, 1.0f + __expf(-pars[4]));
    float shm1 = 0.02f + 0.96f * __fdividef(1.0f, 1.0f + __expf(-pars[5]));
    float shf0 = 0.02f + 0.96f * __fdividef(1.0f, 1.0f + __expf(-pars[6]));
    float shf1 = 0.02f + 0.96f * __fdividef(1.0f, 1.0f + __expf(-pars[7]));
    float V = __expf(pars[8]);

    float r0 = M0 * shm0, r1 = M1 * shm1, r2 = M2;
    float c0 = F0 * shf0, c1 = F1 * shf1, c2 = F2;
    float um0 = M0 * (1.0f - shm0), um1 = M1 * (1.0f - shm1);
    float uf0 = F0 * (1.0f - shf0), uf1 = F1 * (1.0f - shf1);

    #pragma unroll
    for (int it = 0; it < 10; it++) {
        float f0 = __fdividef(r0, A00 + A01 + A02 + EPSF);
        float f1 = __fdividef(r1, A10 + A11 + A12 + EPSF);
        float f2 = __fdividef(r2, A20 + A21 + A22 + EPSF);
        A00 *= f0; A01 *= f0; A02 *= f0;
        A10 *= f1; A11 *= f1; A12 *= f1;
        A20 *= f2; A21 *= f2; A22 *= f2;
        float g0 = __fdividef(c0, A00 + A10 + A20 + EPSF);
        float g1 = __fdividef(c1, A01 + A11 + A21 + EPSF);
        float g2 = __fdividef(c2, A02 + A12 + A22 + EPSF);
        A00 *= g0; A10 *= g0; A20 *= g0;
        A01 *= g1; A11 *= g1; A21 *= g1;
        A02 *= g2; A12 *= g2; A22 *= g2;
    }

    float4* o = reinterpret_cast<float4*>(out_mus + (size_t)row * 16);
    o[0] = make_float4(A00, A01, A02, um0);
    o[1] = make_float4(A10, A11, A12, um1);
    o[2] = make_float4(A20, A21, A22, 0.0f);
    o[3] = make_float4(uf0, uf1, F2 * 0.0f, 0.0f);
    out_V[row] = V;
}

__global__ __launch_bounds__(THREADS)
void sinkhorn_unmatched_kernel(
    const float* __restrict__ margins,
    const float* __restrict__ W1, const float* __restrict__ b1,
    const float* __restrict__ W2, const float* __restrict__ b2,
    const float* __restrict__ W3, const float* __restrict__ b3,
    const float* __restrict__ W4, const float* __restrict__ b4,
    float* __restrict__ out_mus, float* __restrict__ out_V, int B)
{
    // W1 transposed + duplicated as (w,w) 64-bit pairs: [64 out][8 in-pad]
    __shared__ unsigned long long sW1d[64 * 8];
    __shared__ unsigned long long sb1d[64];
    __shared__ float sW2[64 * 32];   // row j = 32 floats = 16 lane-pairs
    __shared__ float sb2[32];
    __shared__ float sW3[32 * 16];
    __shared__ float sb3[16];
    __shared__ float sW4[16 * 12];   // padded 9 -> 12
    __shared__ float sb4[12];

    const int tid = threadIdx.x;
    for (int i = tid; i < 64 * 8; i += THREADS) {
        int j = i >> 3, k = i & 7;
        float w = (k < 6) ? W1[k * 64 + j] : 0.0f;
        sW1d[i] = pack2(w, w);
    }
    for (int i = tid; i < 64; i += THREADS) { float b = b1[i]; sb1d[i] = pack2(b, b); }
    for (int i = tid; i < 64 * 32; i += THREADS) sW2[i] = W2[i];
    for (int i = tid; i < 32; i += THREADS) sb2[i] = b2[i];
    for (int i = tid; i < 32 * 16; i += THREADS) sW3[i] = W3[i];
    for (int i = tid; i < 16; i += THREADS) sb3[i] = b3[i];
    for (int i = tid; i < 16 * 12; i += THREADS) {
        int r = i / 12, c = i % 12;
        sW4[i] = (c < 9) ? W4[r * 9 + c] : 0.0f;
    }
    for (int i = tid; i < 12; i += THREADS) sb4[i] = (i < 9) ? b4[i] : 0.0f;
    __syncthreads();

    int rowA = blockIdx.x * (2 * THREADS) + tid;
    int rowB = rowA + THREADS;
    int rA = rowA < B ? rowA : B - 1;
    int rB = rowB < B ? rowB : B - 1;

    // margins: 6 floats per row, 8B-aligned -> float2 loads
    const float2* m2 = reinterpret_cast<const float2*>(margins);
    float2 a0 = m2[rA * 3 + 0], a1 = m2[rA * 3 + 1], a2 = m2[rA * 3 + 2];
    float2 b0 = m2[rB * 3 + 0], b1v = m2[rB * 3 + 1], b2v = m2[rB * 3 + 2];
    float xA[6] = { a0.x, a0.y, a1.x, a1.y, a2.x, a2.y };
    float xB[6] = { b0.x, b0.y, b1v.x, b1v.y, b2v.x, b2v.y };

    // packed over rows for L1 input broadcast
    unsigned long long px[6];
    #pragma unroll
    for (int i = 0; i < 6; i++) px[i] = pack2(xA[i], xB[i]);

    // ---- fused L1 (6->64) + L2 (64->32): h2 accumulators packed over outputs ----
    unsigned long long accA[16], accB[16];
    {
        const ulonglong2* bias = reinterpret_cast<const ulonglong2*>(sb2);
        #pragma unroll
        for (int q = 0; q < 8; q++) {
            ulonglong2 t = bias[q];
            accA[2 * q] = t.x; accA[2 * q + 1] = t.y;
            accB[2 * q] = t.x; accB[2 * q + 1] = t.y;
        }
    }
    #pragma unroll 8
    for (int j = 0; j < 64; j++) {
        const ulonglong2* w1 = reinterpret_cast<const ulonglong2*>(sW1d + j * 8);
        ulonglong2 w10 = w1[0], w11 = w1[1], w12 = w1[2];
        unsigned long long h = sb1d[j];
        h = fma2(px[0], w10.x, h);
        h = fma2(px[1], w10.y, h);
        h = fma2(px[2], w11.x, h);
        h = fma2(px[3], w11.y, h);
        h = fma2(px[4], w12.x, h);
        h = fma2(px[5], w12.y, h);
        float ha, hb; unpack2(h, ha, hb);
        ha = fmaxf(ha, 0.0f); hb = fmaxf(hb, 0.0f);
        unsigned long long paa = pack2(ha, ha), pbb = pack2(hb, hb);
        const ulonglong2* w2 = reinterpret_cast<const ulonglong2*>(sW2 + j * 32);
        #pragma unroll
        for (int q = 0; q < 8; q++) {
            ulonglong2 w = w2[q];
            accA[2 * q]     = fma2(paa, w.x, accA[2 * q]);
            accA[2 * q + 1] = fma2(paa, w.y, accA[2 * q + 1]);
            accB[2 * q]     = fma2(pbb, w.x, accB[2 * q]);
            accB[2 * q + 1] = fma2(pbb, w.y, accB[2 * q + 1]);
        }
    }

    // ---- L3 (32->16): relu(h2) consumed lazily ----
    unsigned long long h3A[8], h3B[8];
    {
        const ulonglong2* bias = reinterpret_cast<const ulonglong2*>(sb3);
        #pragma unroll
        for (int q = 0; q < 4; q++) {
            ulonglong2 t = bias[q];
            h3A[2 * q] = t.x; h3A[2 * q + 1] = t.y;
            h3B[2 * q] = t.x; h3B[2 * q + 1] = t.y;
        }
    }
    #pragma unroll 4
    for (int jp = 0; jp < 16; jp++) {
        float a0f, a1f, b0f, b1f;
        unpack2(accA[jp], a0f, a1f);
        unpack2(accB[jp], b0f, b1f);
        a0f = fmaxf(a0f, 0.0f); a1f = fmaxf(a1f, 0.0f);
        b0f = fmaxf(b0f, 0.0f); b1f = fmaxf(b1f, 0.0f);
        #pragma unroll
        for (int s = 0; s < 2; s++) {
            int j = 2 * jp + s;
            float ha = s ? a1f : a0f;
            float hb = s ? b1f : b0f;
            unsigned long long paa = pack2(ha, ha), pbb = pack2(hb, hb);
            const ulonglong2* w3 = reinterpret_cast<const ulonglong2*>(sW3 + j * 16);
            #pragma unroll
            for (int q = 0; q < 4; q++) {
                ulonglong2 w = w3[q];
                h3A[2 * q]     = fma2(paa, w.x, h3A[2 * q]);
                h3A[2 * q + 1] = fma2(paa, w.y, h3A[2 * q + 1]);
                h3B[2 * q]     = fma2(pbb, w.x, h3B[2 * q]);
                h3B[2 * q + 1] = fma2(pbb, w.y, h3B[2 * q + 1]);
            }
        }
    }

    // ---- L4 (16->9, padded 12) ----
    unsigned long long pA[6], pB[6];
    {
        const ulonglong2* bias = reinterpret_cast<const ulonglong2*>(sb4);
        #pragma unroll
        for (int q = 0; q < 3; q++) {
            ulonglong2 t = bias[q];
            pA[2 * q] = t.x; pA[2 * q + 1] = t.y;
            pB[2 * q] = t.x; pB[2 * q + 1] = t.y;
        }
    }
    #pragma unroll 4
    for (int jp = 0; jp < 8; jp++) {
        float a0f, a1f, b0f, b1f;
        unpack2(h3A[jp], a0f, a1f);
        unpack2(h3B[jp], b0f, b1f);
        a0f = fmaxf(a0f, 0.0f); a1f = fmaxf(a1f, 0.0f);
        b0f = fmaxf(b0f, 0.0f); b1f = fmaxf(b1f, 0.0f);
        #pragma unroll
        for (int s = 0; s < 2; s++) {
            int j = 2 * jp + s;
            float ha = s ? a1f : a0f;
            float hb = s ? b1f : b0f;
            unsigned long long paa = pack2(ha, ha), pbb = pack2(hb, hb);
            const ulonglong2* w4 = reinterpret_cast<const ulonglong2*>(sW4 + j * 12);
            #pragma unroll
            for (int q = 0; q < 3; q++) {
                ulonglong2 w = w4[q];
                pA[2 * q]     = fma2(paa, w.x, pA[2 * q]);
                pA[2 * q + 1] = fma2(paa, w.y, pA[2 * q + 1]);
                pB[2 * q]     = fma2(pbb, w.x, pB[2 * q]);
                pB[2 * q + 1] = fma2(pbb, w.y, pB[2 * q + 1]);
            }
        }
    }

    float parsA[12], parsB[12];
    #pragma unroll
    for (int q = 0; q < 6; q++) {
        unpack2(pA[q], parsA[2 * q], parsA[2 * q + 1]);
        unpack2(pB[q], parsB[2 * q], parsB[2 * q + 1]);
    }

    if (rowA < B) head_and_store(xA, parsA, out_mus, out_V, rowA);
    if (rowB < B) head_and_store(xB, parsB, out_mus, out_V, rowB);
}

extern "C" void kernel_launch(void* const* d_in, const int* in_sizes, int n_in,
                              void* d_out, int out_size)
{
    const float* margins = (const float*)d_in[0];
    const float* W1 = (const float*)d_in[1];
    const float* b1 = (const float*)d_in[2];
    const float* W2 = (const float*)d_in[3];
    const float* b2 = (const float*)d_in[4];
    const float* W3 = (const float*)d_in[5];
    const float* b3 = (const float*)d_in[6];
    const float* W4 = (const float*)d_in[7];
    const float* b4 = (const float*)d_in[8];

    int B = in_sizes[0] / 6;
    float* out_mus = (float*)d_out;
    float* out_V = (float*)d_out + (size_t)B * 16;

    int rows_per_block = 2 * THREADS;
    int blocks = (B + rows_per_block - 1) / rows_per_block;
    sinkhorn_unmatched_kernel<<<blocks, THREADS>>>(
        margins, W1, b1, W2, b2, W3, b3, W4, b4, out_mus, out_V, B);
}